// round 7
// baseline (speedup 1.0000x reference)
#include <cuda_runtime.h>
#include <math.h>

#define B_   8
#define S_   4096
#define H_   1024
#define R_   (B_ * H_)
#define CAP  128
// exact threshold in lg2 domain: ln(x)+g > 3.3  <=>  lg2(x)+g/ln2 > 3.3/ln2
#define TAU_CHK   4.7610f
#define INV_LN2   1.44269504f
// integer-domain conservative filter (superset; slack 0.0875 lg2):
//   pass if (float)as_int(x) > K' - g*C',  C'=INV_LN2*2^23, K'=(tau2+127-0.0875)*2^23
#define FILT_C   12102202.0f
#define FILT_K   1104556453.0f

// ---------------- device scratch (zero-initialized at load; select restores) ----------------
__device__ float2 g_buf[R_ * CAP];   // survivor (x, g) per row
__device__ int    g_cnt[R_];
__device__ float  g_pooled[R_];

__device__ __forceinline__ float neg_inf() { return __int_as_float(0xff800000); }

// ---------------- 1: streaming filter ----------------
// Block tile: 128 h x 64 s. smem: sg4[s*32 + (hq ^ (s>>2))] (2-way STS max, LDS.128 clean).
// Phase 2: ALU-only predicate mask, then aggregated deferred atomics (1 round trip).
__global__ __launch_bounds__(256, 4) void k_filter(const float* __restrict__ hidden,
                                                   const float* __restrict__ gumbel) {
    __shared__ float4 sg4[64 * 32];          // 32 KB
    float* sg = (float*)sg4;

    int blk  = blockIdx.x;                   // 0..4095
    int sblk = blk & 63;
    int hblk = (blk >> 6) & 7;
    int b    = blk >> 9;
    int s0   = sblk * 64;
    int h0   = hblk * 128;
    int w    = threadIdx.x >> 5;
    int lane = threadIdx.x & 31;

    // ---- phase 1: gumbel [128h x 64s] -> smem transposed (front-batched loads) ----
    {
        int c  = lane & 15;                  // float4 chunk along s
        int hr = lane >> 4;
        const float4* gb = (const float4*)(gumbel + ((size_t)(b * H_ + h0)) * S_ + s0);
        float4 gr[8];
#pragma unroll
        for (int a = 0; a < 8; ++a) {
            int hl = w * 16 + 2 * a + hr;
            gr[a] = __ldcs(&gb[(size_t)hl * (S_ / 4) + c]);
        }
#pragma unroll
        for (int a = 0; a < 8; ++a) {
            int hl = w * 16 + 2 * a + hr;
            int hq = hl >> 2, hk = hl & 3;
            int sw = (hq ^ c) << 2;
            sg[(4 * c + 0) * 128 + sw + hk] = gr[a].x;
            sg[(4 * c + 1) * 128 + sw + hk] = gr[a].y;
            sg[(4 * c + 2) * 128 + sw + hk] = gr[a].z;
            sg[(4 * c + 3) * 128 + sw + hk] = gr[a].w;
        }
    }
    __syncthreads();

    // ---- phase 2: warp w handles s in [w*8, w*8+8), lane = h-quad ----
    const float4* hbase = (const float4*)(hidden + ((size_t)b * S_ + s0 + w * 8) * H_ + h0) + lane;
    int rb = b * H_ + h0 + lane * 4;

    float4 xs[8];
#pragma unroll
    for (int j = 0; j < 8; ++j)
        xs[j] = __ldcs(&hbase[(size_t)j * (H_ / 4)]);

    // predicate pass: pure ALU, no atomics, no stores
    unsigned mask = 0;
#pragma unroll
    for (int j = 0; j < 8; ++j) {
        int s = w * 8 + j;
        float4 g4 = sg4[s * 32 + (lane ^ (s >> 2))];
        if (__int2float_rn(__float_as_int(xs[j].x)) > fmaf(g4.x, -FILT_C, FILT_K)) mask |= 1u << (4 * j + 0);
        if (__int2float_rn(__float_as_int(xs[j].y)) > fmaf(g4.y, -FILT_C, FILT_K)) mask |= 1u << (4 * j + 1);
        if (__int2float_rn(__float_as_int(xs[j].z)) > fmaf(g4.z, -FILT_C, FILT_K)) mask |= 1u << (4 * j + 2);
        if (__int2float_rn(__float_as_int(xs[j].w)) > fmaf(g4.w, -FILT_C, FILT_K)) mask |= 1u << (4 * j + 3);
    }

    if (__any_sync(0xffffffffu, mask != 0u)) {
        // aggregated atomics: one predicated atomicAdd per row (<=4), all independent
        int p0 = 0, p1 = 0, p2 = 0, p3 = 0;
        int c0 = __popc(mask & 0x11111111u);
        int c1 = __popc(mask & 0x22222222u);
        int c2 = __popc(mask & 0x44444444u);
        int c3 = __popc(mask & 0x88888888u);
        if (c0) p0 = atomicAdd(&g_cnt[rb + 0], c0);
        if (c1) p1 = atomicAdd(&g_cnt[rb + 1], c1);
        if (c2) p2 = atomicAdd(&g_cnt[rb + 2], c2);
        if (c3) p3 = atomicAdd(&g_cnt[rb + 3], c3);

        // stores: slot = base + (rank of this element within its row's mask bits)
#pragma unroll
        for (int j = 0; j < 8; ++j) {
            if (mask & (0xFu << (4 * j))) {
                int s = w * 8 + j;
                float4 g4 = sg4[s * 32 + (lane ^ (s >> 2))];
                unsigned below = (1u << (4 * j)) - 1u;
                if (mask & (1u << (4 * j + 0))) {
                    int p = p0 + __popc(mask & 0x11111111u & below);
                    if (p < CAP) g_buf[(rb + 0) * CAP + p] = make_float2(xs[j].x, g4.x);
                }
                if (mask & (1u << (4 * j + 1))) {
                    int p = p1 + __popc(mask & 0x22222222u & below);
                    if (p < CAP) g_buf[(rb + 1) * CAP + p] = make_float2(xs[j].y, g4.y);
                }
                if (mask & (1u << (4 * j + 2))) {
                    int p = p2 + __popc(mask & 0x44444444u & below);
                    if (p < CAP) g_buf[(rb + 2) * CAP + p] = make_float2(xs[j].z, g4.z);
                }
                if (mask & (1u << (4 * j + 3))) {
                    int p = p3 + __popc(mask & 0x88888888u & below);
                    if (p < CAP) g_buf[(rb + 3) * CAP + p] = make_float2(xs[j].w, g4.w);
                }
            }
        }
    }
}

// ---------------- 2: per-row top-8 over survivors (+ inline exact fallback) ----------------
__global__ __launch_bounds__(256) void k_select(const float* __restrict__ hidden,
                                                const float* __restrict__ gumbel) {
    int row  = (blockIdx.x * blockDim.x + threadIdx.x) >> 5;
    int lane = threadIdx.x & 31;
    if (row >= R_) return;

    const float NI = neg_inf();
    int cnt = g_cnt[row];
    if (lane == 0) g_cnt[row] = 0;           // restore for next graph replay

    float sum = 0.f;
    bool fast = false;

    if (cnt <= CAP) {
        // exact scores for <=128 survivors (MUFU cheap here)
        float sc0 = NI, sc1 = NI, sc2 = NI, sc3 = NI;
        float v0 = 0.f, v1 = 0.f, v2 = 0.f, v3 = 0.f;
        int base = row * CAP;
        if (lane      < cnt) { float2 c = g_buf[base + lane];      v0 = c.x; sc0 = fmaf(c.y, INV_LN2, __log2f(c.x)); }
        if (lane + 32 < cnt) { float2 c = g_buf[base + lane + 32]; v1 = c.x; sc1 = fmaf(c.y, INV_LN2, __log2f(c.x)); }
        if (lane + 64 < cnt) { float2 c = g_buf[base + lane + 64]; v2 = c.x; sc2 = fmaf(c.y, INV_LN2, __log2f(c.x)); }
        if (lane + 96 < cnt) { float2 c = g_buf[base + lane + 96]; v3 = c.x; sc3 = fmaf(c.y, INV_LN2, __log2f(c.x)); }

        int npass = (sc0 > TAU_CHK) + (sc1 > TAU_CHK) + (sc2 > TAU_CHK) + (sc3 > TAU_CHK);
#pragma unroll
        for (int off = 16; off > 0; off >>= 1)
            npass += __shfl_xor_sync(0xffffffffu, npass, off);

        if (npass >= 8) {
            fast = true;
            for (int round = 0; round < 8; ++round) {
                float bs = sc0, bv = v0; int bi = 0;
                if (sc1 > bs) { bs = sc1; bv = v1; bi = 1; }
                if (sc2 > bs) { bs = sc2; bv = v2; bi = 2; }
                if (sc3 > bs) { bs = sc3; bv = v3; bi = 3; }
                float m = bs;
#pragma unroll
                for (int off = 16; off > 0; off >>= 1)
                    m = fmaxf(m, __shfl_xor_sync(0xffffffffu, m, off));
                unsigned ball = __ballot_sync(0xffffffffu, bs == m);
                int src = __ffs(ball) - 1;
                sum += __shfl_sync(0xffffffffu, bv, src);
                if (lane == src) {
                    if      (bi == 0) sc0 = NI;
                    else if (bi == 1) sc1 = NI;
                    else if (bi == 2) sc2 = NI;
                    else              sc3 = NI;
                }
            }
        }
    }

    if (!fast) {
        // exact fallback (rare; expected never): warp rescans the full row
        int b = row >> 10;
        int h = row & (H_ - 1);
        const float* hp = hidden + (size_t)b * S_ * H_ + h;
        const float* gp = gumbel + (size_t)row * S_;

        float lsc[8], lv[8];
#pragma unroll
        for (int j = 0; j < 8; ++j) { lsc[j] = NI; lv[j] = 0.f; }

        for (int s = lane; s < S_; s += 32) {
            float x = hp[(size_t)s * H_];
            float g = gp[s];
            float sc = (x > 0.f) ? fmaf(g, INV_LN2, __log2f(x)) : NI;
            if (sc > lsc[7]) {
                lsc[7] = sc; lv[7] = x;
#pragma unroll
                for (int j = 7; j > 0; --j) {
                    if (lsc[j] > lsc[j - 1]) {
                        float ts = lsc[j]; lsc[j] = lsc[j - 1]; lsc[j - 1] = ts;
                        float tv = lv[j];  lv[j]  = lv[j - 1];  lv[j - 1]  = tv;
                    }
                }
            }
        }
        sum = 0.f;
        int ptr = 0;
        for (int round = 0; round < 8; ++round) {
            float cand = NI, cval = 0.f;
#pragma unroll
            for (int j = 0; j < 8; ++j)
                if (j == ptr) { cand = lsc[j]; cval = lv[j]; }
            float m = cand;
#pragma unroll
            for (int off = 16; off > 0; off >>= 1)
                m = fmaxf(m, __shfl_xor_sync(0xffffffffu, m, off));
            unsigned ball = __ballot_sync(0xffffffffu, (cand == m) && (ptr < 8));
            if (ball == 0u) continue;        // remaining are -inf: contributes 0 (matches ref)
            int src = __ffs(ball) - 1;
            sum += __shfl_sync(0xffffffffu, cval, src);
            if (lane == src) ptr++;
        }
    }

    if (lane == 0) g_pooled[row] = sum;
}

// ---------------- 3: out = tanh(pooled @ W^T + bias) ----------------
__global__ __launch_bounds__(256) void k_gemm(const float* __restrict__ W,
                                              const float* __restrict__ bias,
                                              float* __restrict__ out) {
    int j = blockIdx.x;
    float acc[8];
#pragma unroll
    for (int bb = 0; bb < 8; ++bb) acc[bb] = 0.f;

    for (int h = threadIdx.x; h < H_; h += 256) {
        float wv = W[(size_t)j * H_ + h];
#pragma unroll
        for (int bb = 0; bb < 8; ++bb)
            acc[bb] += g_pooled[bb * H_ + h] * wv;
    }
#pragma unroll
    for (int bb = 0; bb < 8; ++bb)
#pragma unroll
        for (int off = 16; off > 0; off >>= 1)
            acc[bb] += __shfl_xor_sync(0xffffffffu, acc[bb], off);

    __shared__ float tot[8];
    if (threadIdx.x < 8) tot[threadIdx.x] = 0.f;
    __syncthreads();
    if ((threadIdx.x & 31) == 0) {
#pragma unroll
        for (int bb = 0; bb < 8; ++bb) atomicAdd(&tot[bb], acc[bb]);
    }
    __syncthreads();
    if (threadIdx.x < 8)
        out[threadIdx.x * H_ + j] = tanhf(tot[threadIdx.x] + bias[j]);
}

// ---------------- launch ----------------
extern "C" void kernel_launch(void* const* d_in, const int* in_sizes, int n_in,
                              void* d_out, int out_size) {
    const float* hidden = (const float*)d_in[0];
    const float* gumbel = (const float*)d_in[1];
    const float* W      = (const float*)d_in[2];
    const float* bias   = (const float*)d_in[3];
    float*       out    = (float*)d_out;
    (void)in_sizes; (void)n_in; (void)out_size;

    k_filter<<<4096, 256>>>(hidden, gumbel);
    k_select<<<1024, 256>>>(hidden, gumbel);
    k_gemm  <<<1024, 256>>>(W, bias, out);
}

// round 8
// speedup vs baseline: 1.0895x; 1.0895x over previous
#include <cuda_runtime.h>
#include <math.h>
#include <stdint.h>

#define B_   8
#define S_   4096
#define H_   1024
#define R_   (B_ * H_)
#define CAP  128
#define TAU_LG2   4.76107544f     /* 3.3 / ln2 */
#define INV_LN2   1.44269504f

// ---------------- device scratch (zero-initialized at load; select restores) ----------------
__device__ float2 g_buf[R_ * CAP];   // survivor (score, value) per row
__device__ int    g_cnt[R_];
__device__ float  g_pooled[R_];

__device__ __forceinline__ float neg_inf() { return __int_as_float(0xff800000); }

__device__ __forceinline__ uint32_t smem_u32(const void* p) {
    uint32_t a;
    asm("{ .reg .u64 t; cvta.to.shared.u64 t, %1; cvt.u32.u64 %0, t; }" : "=r"(a) : "l"(p));
    return a;
}

__device__ __forceinline__ void flt_test(float x, float g, int r) {
    float sc = fmaf(g, INV_LN2, __log2f(x));  // NaN (x<0) / -inf (x==0): never > TAU
    if (sc > TAU_LG2) {
        int p = atomicAdd(&g_cnt[r], 1);
        if (p < CAP) g_buf[r * CAP + p] = make_float2(sc, x);
    }
}

// ---------------- 1: streaming filter ----------------
// Tile: 128 h x 64 s.  Gumbel: cp.async.bulk (TMA path) -> staging smem, then
// smem->smem transpose into swizzled layout sg4[s*32 + (hq^(s>>2))].
// Hidden: LDG.128 front-batched BEFORE the mbarrier wait (streams overlap).
__global__ __launch_bounds__(256) void k_filter(const float* __restrict__ hidden,
                                                const float* __restrict__ gumbel) {
    extern __shared__ float4 smem_dyn[];
    float4* stag = smem_dyn;                 // 32 KB: staging [128h][16 float4 along s]
    float4* sg4  = smem_dyn + 64 * 32;       // 32 KB: transposed+swizzled
    float*  sg   = (float*)sg4;
    uint64_t* mbar_st = (uint64_t*)(smem_dyn + 2 * 64 * 32);
    uint32_t mbar = smem_u32(mbar_st);

    int blk  = blockIdx.x;                   // 0..4095
    int sblk = blk & 63;
    int hblk = (blk >> 6) & 7;
    int b    = blk >> 9;
    int s0   = sblk * 64;
    int h0   = hblk * 128;
    int tid  = threadIdx.x;
    int w    = tid >> 5;
    int lane = tid & 31;

    if (tid == 0)
        asm volatile("mbarrier.init.shared.b64 [%0], %1;" :: "r"(mbar), "r"(1) : "memory");
    __syncthreads();

    // ---- issue gumbel bulk copies: 128 rows x 256B ----
    if (tid == 0)
        asm volatile("mbarrier.arrive.expect_tx.shared.b64 _, [%0], %1;"
                     :: "r"(mbar), "r"(128 * 256) : "memory");
    if (tid < 128) {
        const float* src = gumbel + ((size_t)(b * H_ + h0 + tid)) * S_ + s0;
        uint32_t dst = smem_u32(stag) + tid * 256;
        asm volatile("cp.async.bulk.shared::cta.global.mbarrier::complete_tx::bytes "
                     "[%0], [%1], %2, [%3];"
                     :: "r"(dst), "l"(src), "r"(256), "r"(mbar) : "memory");
    }

    // ---- overlap: front-batch hidden LDG.128 (warp w -> s in [w*8, w*8+8)) ----
    const float4* hbase = (const float4*)(hidden + ((size_t)b * S_ + s0 + w * 8) * H_ + h0) + lane;
    float4 xs[8];
#pragma unroll
    for (int j = 0; j < 8; ++j)
        xs[j] = __ldcs(&hbase[(size_t)j * (H_ / 4)]);

    // ---- wait for gumbel ----
    {
        uint32_t done;
        asm volatile("{\n\t.reg .pred p;\n\t"
                     "mbarrier.try_wait.parity.shared.b64 p, [%1], %2;\n\t"
                     "selp.b32 %0, 1, 0, p;\n\t}"
                     : "=r"(done) : "r"(mbar), "r"(0) : "memory");
        while (!done) {
            asm volatile("{\n\t.reg .pred p;\n\t"
                         "mbarrier.try_wait.parity.shared.b64 p, [%1], %2;\n\t"
                         "selp.b32 %0, 1, 0, p;\n\t}"
                         : "=r"(done) : "r"(mbar), "r"(0) : "memory");
        }
    }
    __syncthreads();   // all tx complete before any thread reads staging

    // ---- transpose staging [h][s] -> sg4 [s][h swizzled] ----
    {
        int c  = lane & 15;                  // s-quad
        int hr = lane >> 4;
#pragma unroll
        for (int a = 0; a < 8; ++a) {
            int hl = w * 16 + 2 * a + hr;    // local h
            float4 g4 = stag[hl * 16 + c];   // LDS.128 from staging
            int hq = hl >> 2, hk = hl & 3;
            int sw = (hq ^ c) << 2;
            sg[(4 * c + 0) * 128 + sw + hk] = g4.x;
            sg[(4 * c + 1) * 128 + sw + hk] = g4.y;
            sg[(4 * c + 2) * 128 + sw + hk] = g4.z;
            sg[(4 * c + 3) * 128 + sw + hk] = g4.w;
        }
    }
    __syncthreads();

    // ---- compute: lane = h-quad ----
    int rb = b * H_ + h0 + lane * 4;
#pragma unroll
    for (int j = 0; j < 8; ++j) {
        int s = w * 8 + j;
        float4 g4 = sg4[s * 32 + (lane ^ (s >> 2))];
        flt_test(xs[j].x, g4.x, rb + 0);
        flt_test(xs[j].y, g4.y, rb + 1);
        flt_test(xs[j].z, g4.z, rb + 2);
        flt_test(xs[j].w, g4.w, rb + 3);
    }
}

// ---------------- 2: per-row top-8 over survivors (+ inline exact fallback) ----------------
__global__ __launch_bounds__(256) void k_select(const float* __restrict__ hidden,
                                                const float* __restrict__ gumbel) {
    int row  = (blockIdx.x * blockDim.x + threadIdx.x) >> 5;
    int lane = threadIdx.x & 31;
    if (row >= R_) return;

    const float NI = neg_inf();
    int cnt = g_cnt[row];
    if (lane == 0) g_cnt[row] = 0;           // restore for next graph replay

    float sum = 0.f;

    if (cnt >= 8 && cnt <= CAP) {
        float sc0 = NI, sc1 = NI, sc2 = NI, sc3 = NI;
        float v0 = 0.f, v1 = 0.f, v2 = 0.f, v3 = 0.f;
        int base = row * CAP;
        if (lane      < cnt) { float2 c = g_buf[base + lane];      sc0 = c.x; v0 = c.y; }
        if (lane + 32 < cnt) { float2 c = g_buf[base + lane + 32]; sc1 = c.x; v1 = c.y; }
        if (lane + 64 < cnt) { float2 c = g_buf[base + lane + 64]; sc2 = c.x; v2 = c.y; }
        if (lane + 96 < cnt) { float2 c = g_buf[base + lane + 96]; sc3 = c.x; v3 = c.y; }

        for (int round = 0; round < 8; ++round) {
            float bs = sc0, bv = v0; int bi = 0;
            if (sc1 > bs) { bs = sc1; bv = v1; bi = 1; }
            if (sc2 > bs) { bs = sc2; bv = v2; bi = 2; }
            if (sc3 > bs) { bs = sc3; bv = v3; bi = 3; }
            float m = bs;
#pragma unroll
            for (int off = 16; off > 0; off >>= 1)
                m = fmaxf(m, __shfl_xor_sync(0xffffffffu, m, off));
            unsigned ball = __ballot_sync(0xffffffffu, bs == m);
            int src = __ffs(ball) - 1;
            sum += __shfl_sync(0xffffffffu, bv, src);
            if (lane == src) {
                if      (bi == 0) sc0 = NI;
                else if (bi == 1) sc1 = NI;
                else if (bi == 2) sc2 = NI;
                else              sc3 = NI;
            }
        }
    } else {
        // exact fallback (rare; expected never): warp rescans the full row
        int b = row >> 10;
        int h = row & (H_ - 1);
        const float* hp = hidden + (size_t)b * S_ * H_ + h;
        const float* gp = gumbel + (size_t)row * S_;

        float lsc[8], lv[8];
#pragma unroll
        for (int j = 0; j < 8; ++j) { lsc[j] = NI; lv[j] = 0.f; }

        for (int s = lane; s < S_; s += 32) {
            float x = hp[(size_t)s * H_];
            float g = gp[s];
            float sc = (x > 0.f) ? fmaf(g, INV_LN2, __log2f(x)) : NI;
            if (sc > lsc[7]) {
                lsc[7] = sc; lv[7] = x;
#pragma unroll
                for (int j = 7; j > 0; --j) {
                    if (lsc[j] > lsc[j - 1]) {
                        float ts = lsc[j]; lsc[j] = lsc[j - 1]; lsc[j - 1] = ts;
                        float tv = lv[j];  lv[j]  = lv[j - 1];  lv[j - 1]  = tv;
                    }
                }
            }
        }
        int ptr = 0;
        for (int round = 0; round < 8; ++round) {
            float cand = NI, cval = 0.f;
#pragma unroll
            for (int j = 0; j < 8; ++j)
                if (j == ptr) { cand = lsc[j]; cval = lv[j]; }
            float m = cand;
#pragma unroll
            for (int off = 16; off > 0; off >>= 1)
                m = fmaxf(m, __shfl_xor_sync(0xffffffffu, m, off));
            unsigned ball = __ballot_sync(0xffffffffu, (cand == m) && (ptr < 8));
            if (ball == 0u) continue;        // remaining are -inf: contributes 0 (matches ref)
            int src = __ffs(ball) - 1;
            sum += __shfl_sync(0xffffffffu, cval, src);
            if (lane == src) ptr++;
        }
    }

    if (lane == 0) g_pooled[row] = sum;
}

// ---------------- 3: out = tanh(pooled @ W^T + bias) ----------------
__global__ __launch_bounds__(256) void k_gemm(const float* __restrict__ W,
                                              const float* __restrict__ bias,
                                              float* __restrict__ out) {
    int j = blockIdx.x;
    float acc[8];
#pragma unroll
    for (int bb = 0; bb < 8; ++bb) acc[bb] = 0.f;

    for (int h = threadIdx.x; h < H_; h += 256) {
        float wv = W[(size_t)j * H_ + h];
#pragma unroll
        for (int bb = 0; bb < 8; ++bb)
            acc[bb] += g_pooled[bb * H_ + h] * wv;
    }
#pragma unroll
    for (int bb = 0; bb < 8; ++bb)
#pragma unroll
        for (int off = 16; off > 0; off >>= 1)
            acc[bb] += __shfl_xor_sync(0xffffffffu, acc[bb], off);

    __shared__ float tot[8];
    if (threadIdx.x < 8) tot[threadIdx.x] = 0.f;
    __syncthreads();
    if ((threadIdx.x & 31) == 0) {
#pragma unroll
        for (int bb = 0; bb < 8; ++bb) atomicAdd(&tot[bb], acc[bb]);
    }
    __syncthreads();
    if (threadIdx.x < 8)
        out[threadIdx.x * H_ + j] = tanhf(tot[threadIdx.x] + bias[j]);
}

// ---------------- launch ----------------
extern "C" void kernel_launch(void* const* d_in, const int* in_sizes, int n_in,
                              void* d_out, int out_size) {
    const float* hidden = (const float*)d_in[0];
    const float* gumbel = (const float*)d_in[1];
    const float* W      = (const float*)d_in[2];
    const float* bias   = (const float*)d_in[3];
    float*       out    = (float*)d_out;
    (void)in_sizes; (void)n_in; (void)out_size;

    const int FILTER_SMEM = 64 * 1024 + 32;   // staging + swizzled + mbarrier
    static int attr_done = 0;
    if (!attr_done) {
        cudaFuncSetAttribute(k_filter, cudaFuncAttributeMaxDynamicSharedMemorySize, FILTER_SMEM);
        attr_done = 1;
    }

    k_filter<<<4096, 256, FILTER_SMEM>>>(hidden, gumbel);
    k_select<<<1024, 256>>>(hidden, gumbel);
    k_gemm  <<<1024, 256>>>(W, bias, out);
}

// round 9
// speedup vs baseline: 1.4052x; 1.2898x over previous
#include <cuda_runtime.h>
#include <math.h>

#define B_   8
#define S_   4096
#define H_   1024
#define R_   (B_ * H_)
#define CAP  128
#define TAU_LG2   4.76107544f     /* 3.3 / ln2 */
#define INV_LN2   1.44269504f

// ---------------- device scratch (zero-initialized at load; select restores) ----------------
__device__ float2 g_buf[R_ * CAP];   // survivor (score, value) per row
__device__ int    g_cnt[R_];
__device__ float  g_pooled[R_];

__device__ __forceinline__ float neg_inf() { return __int_as_float(0xff800000); }

__device__ __forceinline__ void flt_test(float x, float g, int r) {
    float sc = fmaf(g, INV_LN2, __log2f(x));  // NaN (x<0) / -inf (x==0): never > TAU
    if (sc > TAU_LG2) {
        int p = atomicAdd(&g_cnt[r], 1);
        if (p < CAP) g_buf[r * CAP + p] = make_float2(sc, x);
    }
}

// ---------------- 1: streaming filter — warp-self-contained 32h x 32s tiles ----------------
// No __syncthreads anywhere: each warp loads its own gumbel lines (full 128B
// lines, coalesced), transposes through a private 4KB smem tile (swizzle
// (h+s)&31: conflict-free store waves AND loads), then streams hidden with
// coalesced LDG.32 (full 128B lines) and filters. 128-thr blocks, 16KB smem
// -> ~14 CTAs/SM, no block-wide barrier bubbles.
__global__ __launch_bounds__(128) void k_filter(const float* __restrict__ hidden,
                                                const float* __restrict__ gumbel) {
    __shared__ float sg[4 * 32 * 32];        // 16 KB: one 32x32 tile per warp

    int blk  = blockIdx.x;                   // 0..8191
    int sidx = blk & 31;                     // 32 s-chunks (of 128)
    int hidx = (blk >> 5) & 31;              // 32 h-chunks (of 32)
    int b    = blk >> 10;                    // 8 batches
    int w    = threadIdx.x >> 5;             // 4 warps
    int lane = threadIdx.x & 31;

    int s0 = sidx * 128 + w * 32;            // this warp's s window
    int h0 = hidx * 32;
    float* st = sg + w * 1024;               // this warp's tile

    // ---- phase A: gumbel [32h x 32s] -> smem transposed (warp-private) ----
    {
        int row4 = lane >> 3;                // 0..3 : h-row within group of 4
        int c    = lane & 7;                 // 0..7 : float4 chunk along s
        const float4* gb = (const float4*)(gumbel + ((size_t)(b * H_ + h0)) * S_ + s0);
        float4 gr[8];
#pragma unroll
        for (int a = 0; a < 8; ++a) {        // 8 instrs x (4 rows x 128B) : full lines
            int hl = a * 4 + row4;
            gr[a] = __ldcs(&gb[(size_t)hl * (S_ / 4) + c]);
        }
#pragma unroll
        for (int a = 0; a < 8; ++a) {
            int hl = a * 4 + row4;
            int sl = 4 * c;
            st[(sl + 0) * 32 + ((hl + sl + 0) & 31)] = gr[a].x;
            st[(sl + 1) * 32 + ((hl + sl + 1) & 31)] = gr[a].y;
            st[(sl + 2) * 32 + ((hl + sl + 2) & 31)] = gr[a].z;
            st[(sl + 3) * 32 + ((hl + sl + 3) & 31)] = gr[a].w;
        }
    }
    __syncwarp();

    // ---- phase B: hidden coalesced (lane = h), gumbel from smem ----
    const float* hbase = hidden + ((size_t)b * S_ + s0) * H_ + h0 + lane;
    int r = b * H_ + h0 + lane;

#pragma unroll
    for (int grp = 0; grp < 4; ++grp) {
        float xs[8];
#pragma unroll
        for (int j = 0; j < 8; ++j)
            xs[j] = __ldcs(&hbase[(size_t)(grp * 8 + j) * H_]);
#pragma unroll
        for (int j = 0; j < 8; ++j) {
            int sl = grp * 8 + j;
            float g = st[sl * 32 + ((lane + sl) & 31)];
            flt_test(xs[j], g, r);
        }
    }
}

// ---------------- 2: per-row top-8 over survivors (+ inline exact fallback) ----------------
__global__ __launch_bounds__(256) void k_select(const float* __restrict__ hidden,
                                                const float* __restrict__ gumbel) {
    int row  = (blockIdx.x * blockDim.x + threadIdx.x) >> 5;
    int lane = threadIdx.x & 31;
    if (row >= R_) return;

    const float NI = neg_inf();
    int cnt = g_cnt[row];
    if (lane == 0) g_cnt[row] = 0;           // restore for next graph replay

    float sum = 0.f;

    if (cnt >= 8 && cnt <= CAP) {
        float sc0 = NI, sc1 = NI, sc2 = NI, sc3 = NI;
        float v0 = 0.f, v1 = 0.f, v2 = 0.f, v3 = 0.f;
        int base = row * CAP;
        if (lane      < cnt) { float2 c = g_buf[base + lane];      sc0 = c.x; v0 = c.y; }
        if (lane + 32 < cnt) { float2 c = g_buf[base + lane + 32]; sc1 = c.x; v1 = c.y; }
        if (lane + 64 < cnt) { float2 c = g_buf[base + lane + 64]; sc2 = c.x; v2 = c.y; }
        if (lane + 96 < cnt) { float2 c = g_buf[base + lane + 96]; sc3 = c.x; v3 = c.y; }

        for (int round = 0; round < 8; ++round) {
            float bs = sc0, bv = v0; int bi = 0;
            if (sc1 > bs) { bs = sc1; bv = v1; bi = 1; }
            if (sc2 > bs) { bs = sc2; bv = v2; bi = 2; }
            if (sc3 > bs) { bs = sc3; bv = v3; bi = 3; }
            float m = bs;
#pragma unroll
            for (int off = 16; off > 0; off >>= 1)
                m = fmaxf(m, __shfl_xor_sync(0xffffffffu, m, off));
            unsigned ball = __ballot_sync(0xffffffffu, bs == m);
            int src = __ffs(ball) - 1;
            sum += __shfl_sync(0xffffffffu, bv, src);
            if (lane == src) {
                if      (bi == 0) sc0 = NI;
                else if (bi == 1) sc1 = NI;
                else if (bi == 2) sc2 = NI;
                else              sc3 = NI;
            }
        }
    } else {
        // exact fallback (rare; expected never): warp rescans the full row
        int b = row >> 10;
        int h = row & (H_ - 1);
        const float* hp = hidden + (size_t)b * S_ * H_ + h;
        const float* gp = gumbel + (size_t)row * S_;

        float lsc[8], lv[8];
#pragma unroll
        for (int j = 0; j < 8; ++j) { lsc[j] = NI; lv[j] = 0.f; }

        for (int s = lane; s < S_; s += 32) {
            float x = hp[(size_t)s * H_];
            float g = gp[s];
            float sc = (x > 0.f) ? fmaf(g, INV_LN2, __log2f(x)) : NI;
            if (sc > lsc[7]) {
                lsc[7] = sc; lv[7] = x;
#pragma unroll
                for (int j = 7; j > 0; --j) {
                    if (lsc[j] > lsc[j - 1]) {
                        float ts = lsc[j]; lsc[j] = lsc[j - 1]; lsc[j - 1] = ts;
                        float tv = lv[j];  lv[j]  = lv[j - 1];  lv[j - 1]  = tv;
                    }
                }
            }
        }
        int ptr = 0;
        for (int round = 0; round < 8; ++round) {
            float cand = NI, cval = 0.f;
#pragma unroll
            for (int j = 0; j < 8; ++j)
                if (j == ptr) { cand = lsc[j]; cval = lv[j]; }
            float m = cand;
#pragma unroll
            for (int off = 16; off > 0; off >>= 1)
                m = fmaxf(m, __shfl_xor_sync(0xffffffffu, m, off));
            unsigned ball = __ballot_sync(0xffffffffu, (cand == m) && (ptr < 8));
            if (ball == 0u) continue;        // remaining are -inf: contributes 0 (matches ref)
            int src = __ffs(ball) - 1;
            sum += __shfl_sync(0xffffffffu, cval, src);
            if (lane == src) ptr++;
        }
    }

    if (lane == 0) g_pooled[row] = sum;
}

// ---------------- 3: out = tanh(pooled @ W^T + bias) ----------------
__global__ __launch_bounds__(256) void k_gemm(const float* __restrict__ W,
                                              const float* __restrict__ bias,
                                              float* __restrict__ out) {
    int j = blockIdx.x;
    float acc[8];
#pragma unroll
    for (int bb = 0; bb < 8; ++bb) acc[bb] = 0.f;

    for (int h = threadIdx.x; h < H_; h += 256) {
        float wv = W[(size_t)j * H_ + h];
#pragma unroll
        for (int bb = 0; bb < 8; ++bb)
            acc[bb] += g_pooled[bb * H_ + h] * wv;
    }
#pragma unroll
    for (int bb = 0; bb < 8; ++bb)
#pragma unroll
        for (int off = 16; off > 0; off >>= 1)
            acc[bb] += __shfl_xor_sync(0xffffffffu, acc[bb], off);

    __shared__ float tot[8];
    if (threadIdx.x < 8) tot[threadIdx.x] = 0.f;
    __syncthreads();
    if ((threadIdx.x & 31) == 0) {
#pragma unroll
        for (int bb = 0; bb < 8; ++bb) atomicAdd(&tot[bb], acc[bb]);
    }
    __syncthreads();
    if (threadIdx.x < 8)
        out[threadIdx.x * H_ + j] = tanhf(tot[threadIdx.x] + bias[j]);
}

// ---------------- launch ----------------
extern "C" void kernel_launch(void* const* d_in, const int* in_sizes, int n_in,
                              void* d_out, int out_size) {
    const float* hidden = (const float*)d_in[0];
    const float* gumbel = (const float*)d_in[1];
    const float* W      = (const float*)d_in[2];
    const float* bias   = (const float*)d_in[3];
    float*       out    = (float*)d_out;
    (void)in_sizes; (void)n_in; (void)out_size;

    k_filter<<<8192, 128>>>(hidden, gumbel);
    k_select<<<1024, 256>>>(hidden, gumbel);
    k_gemm  <<<1024, 256>>>(W, bias, out);
}